// round 6
// baseline (speedup 1.0000x reference)
#include <cuda_runtime.h>

// DigitCaps dynamic routing, fused. B=64, R=6912, I=8, C=10, O=16, 3 iters.
//
//   k_transpose : x[B,R,I] -> xT[j=r*2+h][b] (float4 transposed)
//   k_pass<0>   : p=W^T x; acc += p;                 last CTA: out0=squash
//   k_pass<1>   : w=exp(p.out0); acc += w*p;         last CTA: out1=squash
//   k_pass<2>   : w=exp(p.(out0+out1)); acc += w*p;  last CTA: squash->d_out
//
// W is read via warp-uniform global LDG (2 distinct lines per warp-inst):
// L1 charges wavefronts per line touched, unlike LDS which charges per lane.
// No smem staging. Thread owns (b, b+16) x 8-o half; dot completed with one
// shfl_xor(16). logits never materialized. Replay-clean state.

#define R_DIM 6912
#define B_DIM 64
#define C_DIM 10
#define R_BLK 64
#define NCTAS ((R_DIM / R_BLK) * C_DIM)   // 1080

typedef unsigned long long u64;

__device__ __align__(16) float g_xT[R_DIM * 2 * B_DIM * 4];   // [r*2+h][b] float4
__device__ __align__(16) float g_acc[C_DIM * B_DIM * 16];
__device__ __align__(16) float g_accw[C_DIM * B_DIM];
__device__ __align__(16) float g_out[2][C_DIM * B_DIM * 16];
__device__ unsigned g_ctr = 0;

__device__ __forceinline__ u64 pack2(float lo, float hi) {
    u64 r; asm("mov.b64 %0, {%1, %2};" : "=l"(r) : "f"(lo), "f"(hi)); return r;
}
__device__ __forceinline__ void unpack2(u64 v, float& lo, float& hi) {
    asm("mov.b64 {%0, %1}, %2;" : "=f"(lo), "=f"(hi) : "l"(v));
}
__device__ __forceinline__ u64 fma2(u64 a, u64 b, u64 c) {
    u64 d; asm("fma.rn.f32x2 %0, %1, %2, %3;" : "=l"(d) : "l"(a), "l"(b), "l"(c)); return d;
}
__device__ __forceinline__ u64 add2(u64 a, u64 b) {
    u64 d; asm("add.rn.f32x2 %0, %1, %2;" : "=l"(d) : "l"(a), "l"(b)); return d;
}

// x as float4 matrix [64][13824] -> [13824][64]
__global__ void k_transpose(const float4* __restrict__ x4) {
    __shared__ float4 tile[32][33];
    const int jb = blockIdx.x * 32;
    const int bb = blockIdx.y * 32;
    const int tx = threadIdx.x, ty = threadIdx.y;   // 32 x 8
    #pragma unroll
    for (int k = 0; k < 32; k += 8)
        tile[ty + k][tx] = x4[(size_t)(bb + ty + k) * (R_DIM * 2) + jb + tx];
    __syncthreads();
    float4* out4 = reinterpret_cast<float4*>(g_xT);
    #pragma unroll
    for (int k = 0; k < 32; k += 8)
        out4[(size_t)(jb + ty + k) * B_DIM + bb + tx] = tile[tx][ty + k];
}

// MODE 0: uniform; 1: w=exp(p.out0); 2: w=exp(p.(out0+out1))
template <int MODE>
__global__ void __launch_bounds__(256, 3)
k_pass(const float* __restrict__ Wg, float* __restrict__ dout) {
    const int c      = blockIdx.y;
    const int rblock = blockIdx.x * R_BLK;
    const int tid    = threadIdx.x;
    const int warp   = tid >> 5;
    const int lane   = tid & 31;
    const int rgroup = warp >> 1;                 // 0..3, each covers 16 r
    const int bhalf  = warp & 1;
    const int oh     = lane >> 4;                 // o-half: 0 or 1
    const int bq     = lane & 15;
    const int b0     = bhalf * 32 + bq;           // owns b0 and b0+16
    const int b1     = b0 + 16;

    __shared__ float sredP[4][B_DIM][16];         // 16 KB
    __shared__ float sredW[4][B_DIM];
    __shared__ unsigned s_rank;

    // out-half vectors for b0, b1 (constant over r)
    u64 ov0[4], ov1[4];
    if (MODE != 0) {
        const u64* p00 = reinterpret_cast<const u64*>(g_out[0] + (c * B_DIM + b0) * 16 + oh * 8);
        const u64* p01 = reinterpret_cast<const u64*>(g_out[0] + (c * B_DIM + b1) * 16 + oh * 8);
        #pragma unroll
        for (int t = 0; t < 4; t++) { ov0[t] = p00[t]; ov1[t] = p01[t]; }
        if (MODE == 2) {
            const u64* p10 = reinterpret_cast<const u64*>(g_out[1] + (c * B_DIM + b0) * 16 + oh * 8);
            const u64* p11 = reinterpret_cast<const u64*>(g_out[1] + (c * B_DIM + b1) * 16 + oh * 8);
            #pragma unroll
            for (int t = 0; t < 4; t++) { ov0[t] = add2(ov0[t], p10[t]); ov1[t] = add2(ov1[t], p11[t]); }
        }
    }

    u64 acc0[4], acc1[4];
    #pragma unroll
    for (int t = 0; t < 4; t++) { acc0[t] = 0ull; acc1[t] = 0ull; }
    float accw0 = 0.0f, accw1 = 0.0f;

    const float4* x4 = reinterpret_cast<const float4*>(g_xT);
    // W row base for this warp's first r, offset to this lane's o-half
    const float* wbase = Wg + ((size_t)c * R_DIM + rblock + rgroup * 16) * 128 + oh * 8;

    #pragma unroll 1
    for (int k = 0; k < 16; k++) {
        const int r = rblock + rgroup * 16 + k;

        // x[b][r][0..7] for b0, b1
        float4 xa0 = x4[(size_t)(r * 2 + 0) * B_DIM + b0];
        float4 xb0 = x4[(size_t)(r * 2 + 1) * B_DIM + b0];
        float4 xa1 = x4[(size_t)(r * 2 + 0) * B_DIM + b1];
        float4 xb1 = x4[(size_t)(r * 2 + 1) * B_DIM + b1];
        const float xf0[8] = {xa0.x, xa0.y, xa0.z, xa0.w, xb0.x, xb0.y, xb0.z, xb0.w};
        const float xf1[8] = {xa1.x, xa1.y, xa1.z, xa1.w, xb1.x, xb1.y, xb1.z, xb1.w};

        // W half-row from GLOBAL, warp-uniform per oh (2 lines per warp-inst)
        const ulonglong2* wp = reinterpret_cast<const ulonglong2*>(wbase + (size_t)k * 128);

        u64 p0[4], p1[4];
        #pragma unroll
        for (int t = 0; t < 4; t++) { p0[t] = 0ull; p1[t] = 0ull; }

        #pragma unroll
        for (int i = 0; i < 8; i++) {
            ulonglong2 wA = wp[i * 4 + 0];   // o-half floats 0..3
            ulonglong2 wB = wp[i * 4 + 1];   // o-half floats 4..7
            u64 xx0 = pack2(xf0[i], xf0[i]);
            u64 xx1 = pack2(xf1[i], xf1[i]);
            p0[0] = fma2(wA.x, xx0, p0[0]); p0[1] = fma2(wA.y, xx0, p0[1]);
            p0[2] = fma2(wB.x, xx0, p0[2]); p0[3] = fma2(wB.y, xx0, p0[3]);
            p1[0] = fma2(wA.x, xx1, p1[0]); p1[1] = fma2(wA.y, xx1, p1[1]);
            p1[2] = fma2(wB.x, xx1, p1[2]); p1[3] = fma2(wB.y, xx1, p1[3]);
        }

        if (MODE == 0) {
            #pragma unroll
            for (int t = 0; t < 4; t++) {
                acc0[t] = add2(acc0[t], p0[t]);
                acc1[t] = add2(acc1[t], p1[t]);
            }
        } else {
            u64 d0 = 0ull, d1 = 0ull;
            #pragma unroll
            for (int t = 0; t < 4; t++) {
                d0 = fma2(p0[t], ov0[t], d0);
                d1 = fma2(p1[t], ov1[t], d1);
            }
            float lo, hi;
            unpack2(d0, lo, hi); float del0 = lo + hi;
            unpack2(d1, lo, hi); float del1 = lo + hi;
            // complete 16-o dot across the two o-half lanes
            del0 += __shfl_xor_sync(0xffffffffu, del0, 16);
            del1 += __shfl_xor_sync(0xffffffffu, del1, 16);
            del0 = fminf(del0, 70.0f); del1 = fminf(del1, 70.0f);
            float w0 = __expf(del0), w1 = __expf(del1);
            accw0 += w0; accw1 += w1;
            u64 w20 = pack2(w0, w0), w21 = pack2(w1, w1);
            #pragma unroll
            for (int t = 0; t < 4; t++) {
                acc0[t] = fma2(p0[t], w20, acc0[t]);
                acc1[t] = fma2(p1[t], w21, acc1[t]);
            }
        }
    }

    // partials -> smem
    {
        float2* s0 = reinterpret_cast<float2*>(&sredP[rgroup][b0][oh * 8]);
        float2* s1 = reinterpret_cast<float2*>(&sredP[rgroup][b1][oh * 8]);
        #pragma unroll
        for (int t = 0; t < 4; t++) {
            float lo, hi;
            unpack2(acc0[t], lo, hi); s0[t] = make_float2(lo, hi);
            unpack2(acc1[t], lo, hi); s1[t] = make_float2(lo, hi);
        }
        if (MODE != 0 && oh == 0) { sredW[rgroup][b0] = accw0; sredW[rgroup][b1] = accw1; }
    }
    __syncthreads();

    // fold 4 rgroups -> global atomics
    for (int idx = tid; idx < B_DIM * 16; idx += 256) {
        const int bb = idx >> 4, o = idx & 15;
        float v = sredP[0][bb][o] + sredP[1][bb][o] + sredP[2][bb][o] + sredP[3][bb][o];
        atomicAdd(&g_acc[c * (B_DIM * 16) + idx], v);
    }
    if (MODE != 0 && tid < B_DIM) {
        float v = sredW[0][tid] + sredW[1][tid] + sredW[2][tid] + sredW[3][tid];
        atomicAdd(&g_accw[c * B_DIM + tid], v);
    }

    // ---- last CTA: squash inline ----
    __threadfence();
    if (tid == 0) s_rank = atomicAdd(&g_ctr, 1);
    __syncthreads();
    if (s_rank == NCTAS - 1) {
        for (int pair = tid; pair < C_DIM * B_DIM; pair += 256) {
            const float* a = g_acc + pair * 16;
            float invw = (MODE == 0) ? (1.0f / (float)R_DIM) : (1.0f / __ldcg(&g_accw[pair]));
            float s[16], sq = 0.0f;
            #pragma unroll
            for (int o = 0; o < 16; o++) { s[o] = __ldcg(a + o) * invw; sq += s[o] * s[o]; }
            float coef = sq / ((1.0f + sq) * sqrtf(sq));
            float* dst = (MODE == 2) ? (dout + pair * 16) : (g_out[MODE] + pair * 16);
            #pragma unroll
            for (int o = 0; o < 16; o++) dst[o] = coef * s[o];
        }
        __syncthreads();
        for (int idx = tid; idx < C_DIM * B_DIM * 16; idx += 256) g_acc[idx] = 0.0f;
        for (int idx = tid; idx < C_DIM * B_DIM; idx += 256) g_accw[idx] = 0.0f;
        if (tid == 0) g_ctr = 0;
    }
}

extern "C" void kernel_launch(void* const* d_in, const int* in_sizes, int n_in,
                              void* d_out, int out_size) {
    const float* x = (const float*)d_in[0];          // [64, 6912, 8]
    const float* W = (const float*)d_in[1];          // [10, 6912, 8, 16]
    float* out = (float*)d_out;                      // [10, 64, 1, 1, 16]

    dim3 tgrid(R_DIM * 2 / 32, B_DIM / 32);          // (432, 2)
    k_transpose<<<tgrid, dim3(32, 8)>>>(reinterpret_cast<const float4*>(x));

    dim3 grid(R_DIM / R_BLK, C_DIM);                 // (108, 10)
    k_pass<0><<<grid, 256>>>(W, nullptr);
    k_pass<1><<<grid, 256>>>(W, nullptr);
    k_pass<2><<<grid, 256>>>(W, out);
}

// round 7
// speedup vs baseline: 1.3216x; 1.3216x over previous
#include <cuda_runtime.h>

// DigitCaps dynamic routing, fused. B=64, R=6912, I=8, C=10, O=16, 3 iters.
//
//   k_transpose : x[B,R,I] -> xT[j=r*2+h][b] (float4 transposed)
//   k_pass<0>   : p=W^T x; acc += p;                 last CTA: out0=squash
//   k_pass<1>   : w=exp(p.out0); acc += w*p;         last CTA: out1=squash
//   k_pass<2>   : w=exp(p.(out0+out1)); acc += w*p;  last CTA: squash->d_out
//
// Thread owns 4 b x 4 o (Nb=4, No=4): 8 LDS.128 of W per warp-k-step feed
// 64 fma2 — half the smem crossbar traffic of Nb=2 at ~85 regs. Dot over 16 o
// completed with shfl_xor(8)+shfl_xor(16) across the 4 oq lane-groups.
// W staged via cp.async. logits never materialized. Replay-clean state.

#define R_DIM 6912
#define B_DIM 64
#define C_DIM 10
#define R_BLK 64
#define NCTAS ((R_DIM / R_BLK) * C_DIM)   // 1080

typedef unsigned long long u64;

__device__ __align__(16) float g_xT[R_DIM * 2 * B_DIM * 4];   // [r*2+h][b] float4
__device__ __align__(16) float g_acc[C_DIM * B_DIM * 16];
__device__ __align__(16) float g_accw[C_DIM * B_DIM];
__device__ __align__(16) float g_out[2][C_DIM * B_DIM * 16];
__device__ unsigned g_ctr = 0;

__device__ __forceinline__ u64 pack2(float lo, float hi) {
    u64 r; asm("mov.b64 %0, {%1, %2};" : "=l"(r) : "f"(lo), "f"(hi)); return r;
}
__device__ __forceinline__ void unpack2(u64 v, float& lo, float& hi) {
    asm("mov.b64 {%0, %1}, %2;" : "=f"(lo), "=f"(hi) : "l"(v));
}
__device__ __forceinline__ u64 fma2(u64 a, u64 b, u64 c) {
    u64 d; asm("fma.rn.f32x2 %0, %1, %2, %3;" : "=l"(d) : "l"(a), "l"(b), "l"(c)); return d;
}
__device__ __forceinline__ u64 add2(u64 a, u64 b) {
    u64 d; asm("add.rn.f32x2 %0, %1, %2;" : "=l"(d) : "l"(a), "l"(b)); return d;
}
__device__ __forceinline__ unsigned smem_u32(const void* p) {
    return (unsigned)__cvta_generic_to_shared(p);
}
__device__ __forceinline__ void cp_async16(unsigned saddr, const void* g) {
    asm volatile("cp.async.cg.shared.global [%0], [%1], 16;" :: "r"(saddr), "l"(g));
}

// x as float4 matrix [64][13824] -> [13824][64]
__global__ void k_transpose(const float4* __restrict__ x4) {
    __shared__ float4 tile[32][33];
    const int jb = blockIdx.x * 32;
    const int bb = blockIdx.y * 32;
    const int tx = threadIdx.x, ty = threadIdx.y;   // 32 x 8
    #pragma unroll
    for (int k = 0; k < 32; k += 8)
        tile[ty + k][tx] = x4[(size_t)(bb + ty + k) * (R_DIM * 2) + jb + tx];
    __syncthreads();
    float4* out4 = reinterpret_cast<float4*>(g_xT);
    #pragma unroll
    for (int k = 0; k < 32; k += 8)
        out4[(size_t)(jb + ty + k) * B_DIM + bb + tx] = tile[tx][ty + k];
}

// MODE 0: uniform; 1: w=exp(p.out0); 2: w=exp(p.(out0+out1))
template <int MODE>
__global__ void __launch_bounds__(256, 3)
k_pass(const float* __restrict__ Wg, float* __restrict__ dout) {
    const int c      = blockIdx.y;
    const int rblock = blockIdx.x * R_BLK;
    const int tid    = threadIdx.x;
    const int warp   = tid >> 5;
    const int lane   = tid & 31;
    const int rgroup = warp >> 1;                 // 0..3, each covers 16 r
    const int bhalf  = warp & 1;
    const int oq     = lane >> 3;                 // o-quarter: 0..3
    const int bq     = lane & 7;
    const int bb     = bhalf * 32 + bq;           // owns bb + {0,8,16,24}

    __shared__ __align__(16) float sW[R_BLK * 128];   // 32 KB
    __shared__ float sredP[4][B_DIM][16];             // 16 KB
    __shared__ float sredW[4][B_DIM];
    __shared__ unsigned s_rank;

    // --- stage W tile (contiguous 32 KB) ---
    {
        const char* src = reinterpret_cast<const char*>(Wg + ((size_t)c * R_DIM + rblock) * 128);
        unsigned dst = smem_u32(sW);
        #pragma unroll
        for (int s = 0; s < 8; s++)
            cp_async16(dst + tid * 16 + s * 4096, src + tid * 16 + s * 4096);
        asm volatile("cp.async.commit_group;");
    }

    // out-quarter vectors for 4 b's (loop-invariant)
    u64 ov[4][2];
    if (MODE != 0) {
        #pragma unroll
        for (int j = 0; j < 4; j++) {
            const u64* p0 = reinterpret_cast<const u64*>(
                g_out[0] + (c * B_DIM + bb + j * 8) * 16 + oq * 4);
            ov[j][0] = p0[0]; ov[j][1] = p0[1];
            if (MODE == 2) {
                const u64* p1 = reinterpret_cast<const u64*>(
                    g_out[1] + (c * B_DIM + bb + j * 8) * 16 + oq * 4);
                ov[j][0] = add2(ov[j][0], p1[0]);
                ov[j][1] = add2(ov[j][1], p1[1]);
            }
        }
    }

    u64 acc[4][2];
    #pragma unroll
    for (int j = 0; j < 4; j++) { acc[j][0] = 0ull; acc[j][1] = 0ull; }
    float accw[4] = {0.0f, 0.0f, 0.0f, 0.0f};

    asm volatile("cp.async.wait_group 0;");
    __syncthreads();

    const float4* x4 = reinterpret_cast<const float4*>(g_xT);
    // per-thread W base: o-quarter oq (one ulonglong2 = 4 floats per i)
    const ulonglong2* wb = reinterpret_cast<const ulonglong2*>(sW) + oq;

    #pragma unroll 1
    for (int k = 0; k < 16; k++) {
        const int rl = rgroup * 16 + k;
        const int r  = rblock + rl;

        u64 p[4][2];
        #pragma unroll
        for (int j = 0; j < 4; j++) { p[j][0] = 0ull; p[j][1] = 0ull; }

        #pragma unroll
        for (int h = 0; h < 2; h++) {
            float4 xv[4];
            #pragma unroll
            for (int j = 0; j < 4; j++)
                xv[j] = x4[(size_t)(r * 2 + h) * B_DIM + bb + j * 8];
            #pragma unroll
            for (int ii = 0; ii < 4; ii++) {
                const int i = h * 4 + ii;
                ulonglong2 wv = wb[rl * 32 + i * 4];   // W[rl][i][oq*4..+4]
                #pragma unroll
                for (int j = 0; j < 4; j++) {
                    float xs = (ii == 0) ? xv[j].x : (ii == 1) ? xv[j].y
                             : (ii == 2) ? xv[j].z : xv[j].w;
                    u64 xx = pack2(xs, xs);
                    p[j][0] = fma2(wv.x, xx, p[j][0]);
                    p[j][1] = fma2(wv.y, xx, p[j][1]);
                }
            }
        }

        if (MODE == 0) {
            #pragma unroll
            for (int j = 0; j < 4; j++) {
                acc[j][0] = add2(acc[j][0], p[j][0]);
                acc[j][1] = add2(acc[j][1], p[j][1]);
            }
        } else {
            #pragma unroll
            for (int j = 0; j < 4; j++) {
                u64 d = fma2(p[j][0], ov[j][0], 0ull);
                d = fma2(p[j][1], ov[j][1], d);
                float lo, hi; unpack2(d, lo, hi);
                float del = lo + hi;
                del += __shfl_xor_sync(0xffffffffu, del, 8);
                del += __shfl_xor_sync(0xffffffffu, del, 16);
                del = fminf(del, 70.0f);
                float w = __expf(del);
                accw[j] += w;
                u64 w2 = pack2(w, w);
                acc[j][0] = fma2(p[j][0], w2, acc[j][0]);
                acc[j][1] = fma2(p[j][1], w2, acc[j][1]);
            }
        }
    }

    // partials -> smem (float4 per (b, oq))
    #pragma unroll
    for (int j = 0; j < 4; j++) {
        float a0, a1, a2, a3;
        unpack2(acc[j][0], a0, a1);
        unpack2(acc[j][1], a2, a3);
        *reinterpret_cast<float4*>(&sredP[rgroup][bb + j * 8][oq * 4]) =
            make_float4(a0, a1, a2, a3);
        if (MODE != 0 && oq == 0) sredW[rgroup][bb + j * 8] = accw[j];
    }
    __syncthreads();

    // fold 4 rgroups -> global atomics
    for (int idx = tid; idx < B_DIM * 16; idx += 256) {
        const int b2 = idx >> 4, o = idx & 15;
        float v = sredP[0][b2][o] + sredP[1][b2][o] + sredP[2][b2][o] + sredP[3][b2][o];
        atomicAdd(&g_acc[c * (B_DIM * 16) + idx], v);
    }
    if (MODE != 0 && tid < B_DIM) {
        float v = sredW[0][tid] + sredW[1][tid] + sredW[2][tid] + sredW[3][tid];
        atomicAdd(&g_accw[c * B_DIM + tid], v);
    }

    // ---- last CTA: squash inline ----
    __threadfence();
    if (tid == 0) s_rank = atomicAdd(&g_ctr, 1);
    __syncthreads();
    if (s_rank == NCTAS - 1) {
        for (int pair = tid; pair < C_DIM * B_DIM; pair += 256) {
            const float* a = g_acc + pair * 16;
            float invw = (MODE == 0) ? (1.0f / (float)R_DIM) : (1.0f / __ldcg(&g_accw[pair]));
            float s[16], sq = 0.0f;
            #pragma unroll
            for (int o = 0; o < 16; o++) { s[o] = __ldcg(a + o) * invw; sq += s[o] * s[o]; }
            float coef = sq / ((1.0f + sq) * sqrtf(sq));
            float* dst = (MODE == 2) ? (dout + pair * 16) : (g_out[MODE] + pair * 16);
            #pragma unroll
            for (int o = 0; o < 16; o++) dst[o] = coef * s[o];
        }
        __syncthreads();
        for (int idx = tid; idx < C_DIM * B_DIM * 16; idx += 256) g_acc[idx] = 0.0f;
        for (int idx = tid; idx < C_DIM * B_DIM; idx += 256) g_accw[idx] = 0.0f;
        if (tid == 0) g_ctr = 0;
    }
}

extern "C" void kernel_launch(void* const* d_in, const int* in_sizes, int n_in,
                              void* d_out, int out_size) {
    const float* x = (const float*)d_in[0];          // [64, 6912, 8]
    const float* W = (const float*)d_in[1];          // [10, 6912, 8, 16]
    float* out = (float*)d_out;                      // [10, 64, 1, 1, 16]

    dim3 tgrid(R_DIM * 2 / 32, B_DIM / 32);          // (432, 2)
    k_transpose<<<tgrid, dim3(32, 8)>>>(reinterpret_cast<const float4*>(x));

    dim3 grid(R_DIM / R_BLK, C_DIM);                 // (108, 10)
    k_pass<0><<<grid, 256>>>(W, nullptr);
    k_pass<1><<<grid, 256>>>(W, nullptr);
    k_pass<2><<<grid, 256>>>(W, out);
}